// round 15
// baseline (speedup 1.0000x reference)
#include <cuda_runtime.h>

// SSIM loss, fused single kernel, f32x2-packed separable 11x11 Gaussian conv.
// 4-channel reformulation: s=cx+cy, d=cx-cy; conv (s, d, s^2, d^2).
//   P=mu_s^2, Q=mu_d^2, A=E[s^2], B=E[d^2]:
//   num = ((P-Q)/2+C1) * ((A-B-P+Q)/2+C2)
//   den = ((P+Q)/2+C1) * ((A+B-P-Q)/2+C2)
// 32x32 tile + halo 5, static SMEM (36.5KB -> 6 blocks/SM). Phase 2:
// channel-set split items (336, FFMA2). Phase 3: 256 items x 4 cols,
// scalar FFMA-imm (rt=1) window accumulation. S2=22 keeps every LDS.128
// 16B-aligned. Epilogue: packed SSIM + fraction tree, one RCP per 4 px.

#define TW 32
#define TH 32
#define HALO 5
#define KS 11
#define HWD 42
#define SWX 44            // ss/sd row stride (floats; 176B rows, 8B-aligned f2)
#define S2  22            // sv2 row stride (u64; EVEN -> LDS.128 16B-aligned)

typedef unsigned long long u64t;

__device__ double g_acc = 0.0;
__device__ unsigned int g_cnt = 0;

__device__ constexpr float GW[11] = {
    0.00102838f, 0.00759876f, 0.03600078f, 0.10936069f, 0.21300553f,
    0.26601173f,
    0.21300553f, 0.10936069f, 0.03600078f, 0.00759876f, 0.00102838f};

__device__ __forceinline__ u64t pk2(float lo, float hi) {
    u64t r; asm("mov.b64 %0,{%1,%2};" : "=l"(r) : "f"(lo), "f"(hi)); return r;
}
__device__ __forceinline__ void upk2(u64t v, float& lo, float& hi) {
    asm("mov.b64 {%0,%1},%2;" : "=f"(lo), "=f"(hi) : "l"(v));
}
__device__ __forceinline__ u64t fma2_(u64t a, u64t b, u64t c) {
    u64t d; asm("fma.rn.f32x2 %0,%1,%2,%3;" : "=l"(d) : "l"(a), "l"(b), "l"(c)); return d;
}
__device__ __forceinline__ u64t mul2_(u64t a, u64t b) {
    u64t d; asm("mul.rn.f32x2 %0,%1,%2;" : "=l"(d) : "l"(a), "l"(b)); return d;
}
__device__ __forceinline__ u64t add2_(u64t a, u64t b) {
    u64t d; asm("add.rn.f32x2 %0,%1,%2;" : "=l"(d) : "l"(a), "l"(b)); return d;
}
__device__ __forceinline__ u64t sub2_(u64t a, u64t b) {
    u64t d; asm("sub.rn.f32x2 %0,%1,%2;" : "=l"(d) : "l"(a), "l"(b)); return d;
}

__device__ __forceinline__ constexpr int WS(int j) { return j < 6 ? j : 10 - j; }

__global__ __launch_bounds__(256, 6)
void ssim_main_k(const float* __restrict__ A, const float* __restrict__ Bp,
                 float* __restrict__ out) {
    __shared__ __align__(16) float ss[HWD][SWX];
    __shared__ __align__(16) float sd[HWD][SWX];
    __shared__ __align__(16) u64t  sv2[4][TH][S2];
    __shared__ float red[8];

    const int tid = threadIdx.x;
    const int tx0 = blockIdx.x * TW;
    const int ty0 = blockIdx.y * TH;
    const size_t base = (size_t)blockIdx.z * (512 * 512);

    u64t wq[6];
#pragma unroll
    for (int j = 0; j < 6; j++) wq[j] = pk2(GW[j], GW[j]);

    // -------- Phase 1: halo load (col pairs), clip, s=cx+cy, d=cx-cy --------
    const bool interior = (blockIdx.x != 0) && (blockIdx.x != 15) &&
                          (blockIdx.y != 0) && (blockIdx.y != 15);
    if (interior) {
#pragma unroll
        for (int i = tid; i < 42 * 21; i += 256) {
            int r = i / 21, c2 = i - r * 21;
            size_t idx = base + (size_t)(ty0 + r - HALO) * 512 + (tx0 + 2 * c2 - HALO);
            float cx0 = __saturatef(__ldg(A + idx));
            float cx1 = __saturatef(__ldg(A + idx + 1));
            float cy0 = __saturatef(__ldg(Bp + idx));
            float cy1 = __saturatef(__ldg(Bp + idx + 1));
            *(float2*)&ss[r][2 * c2] = make_float2(cx0 + cy0, cx1 + cy1);
            *(float2*)&sd[r][2 * c2] = make_float2(cx0 - cy0, cx1 - cy1);
        }
    } else {
#pragma unroll
        for (int i = tid; i < 42 * 21; i += 256) {
            int r = i / 21, c2 = i - r * 21;
            int gy = ty0 + r - HALO;
            int gx = tx0 + 2 * c2 - HALO;
            float cx0 = 0.f, cy0 = 0.f, cx1 = 0.f, cy1 = 0.f;
            bool rowok = (unsigned)gy < 512u;
            if (rowok && (unsigned)gx < 512u) {
                size_t idx = base + (size_t)gy * 512 + gx;
                cx0 = __saturatef(__ldg(A + idx));
                cy0 = __saturatef(__ldg(Bp + idx));
            }
            if (rowok && (unsigned)(gx + 1) < 512u) {
                size_t idx = base + (size_t)gy * 512 + gx + 1;
                cx1 = __saturatef(__ldg(A + idx));
                cy1 = __saturatef(__ldg(Bp + idx));
            }
            *(float2*)&ss[r][2 * c2] = make_float2(cx0 + cy0, cx1 + cy1);
            *(float2*)&sd[r][2 * c2] = make_float2(cx0 - cy0, cx1 - cy1);
        }
    }
    __syncthreads();

    // -------- Phase 2: vertical conv, channel-set split items ----------------
    // 336 items = 2 chsets (s | d) x 8 rowgroups (4 rows) x 21 col-pairs.
    for (int i = tid; i < 336; i += 256) {
        const int isD = (i >= 168) ? 1 : 0;
        const int j0 = i - 168 * isD;
        const int g = j0 / 21;
        const int k = j0 - 21 * g;
        const int r0 = g * 4;
        const float* p = isD ? &sd[r0][2 * k] : &ss[r0][2 * k];
        u64t a1[4] = {0, 0, 0, 0}, a2[4] = {0, 0, 0, 0};
#pragma unroll
        for (int p14 = 0; p14 < 14; p14++) {
            float2 vv = *(const float2*)(p + p14 * SWX);
            u64t V = pk2(vv.x, vv.y);
            u64t VV = mul2_(V, V);
#pragma unroll
            for (int o = 0; o < 4; o++) {
                int j = p14 - o;
                if (j >= 0 && j < KS) {
                    u64t w = wq[WS(j)];
                    a1[o] = fma2_(w, V,  a1[o]);
                    a2[o] = fma2_(w, VV, a2[o]);
                }
            }
        }
#pragma unroll
        for (int o = 0; o < 4; o++) {
            int row = r0 + o;
            sv2[isD][row][k]     = a1[o];   // ch0 = mu_s, ch1 = mu_d
            sv2[2 + isD][row][k] = a2[o];   // ch2 = A,    ch3 = B
        }
    }
    __syncthreads();

    // -------- Phase 3: horizontal conv (scalar FFMA-imm) + SSIM, 256 items ---
    // item = 1 row x 4 output cols; 32 rows x 8 colgroups.
    float lsum = 0.f;
    {
        const int r  = tid >> 3;
        const int cg = tid & 7;
        const int m0 = 2 * cg;           // granules m0 .. m0+6 (cols 4cg..4cg+13)
        float acc[4][4];                 // [channel][output col]
#pragma unroll
        for (int ch = 0; ch < 4; ch++) {
            const u64t* rowp = &sv2[ch][r][m0];   // 16B-aligned (S2, m0 even)
            u64t E[7];
            ulonglong2 q0 = *(const ulonglong2*)(rowp);
            ulonglong2 q1 = *(const ulonglong2*)(rowp + 2);
            ulonglong2 q2 = *(const ulonglong2*)(rowp + 4);
            E[0] = q0.x; E[1] = q0.y; E[2] = q1.x; E[3] = q1.y;
            E[4] = q2.x; E[5] = q2.y; E[6] = rowp[6];
            float f[14];
#pragma unroll
            for (int t = 0; t < 7; t++) upk2(E[t], f[2 * t], f[2 * t + 1]);
#pragma unroll
            for (int o = 0; o < 4; o++) {
                float a = GW[0] * f[o];
#pragma unroll
                for (int j = 1; j < KS; j++)
                    a = fmaf(GW[j], f[o + j], a);   // FFMA-imm, rt=1
                acc[ch][o] = a;
            }
        }
        const u64t HALF = pk2(0.5f, 0.5f);
        const u64t C1q = pk2(1e-4f, 1e-4f);
        const u64t C2q = pk2(9e-4f, 9e-4f);
        float rr[2], qq[2];
#pragma unroll
        for (int o = 0; o < 2; o++) {
            u64t mus = pk2(acc[0][2 * o], acc[0][2 * o + 1]);
            u64t mud = pk2(acc[1][2 * o], acc[1][2 * o + 1]);
            u64t Aq  = pk2(acc[2][2 * o], acc[2][2 * o + 1]);
            u64t Bq  = pk2(acc[3][2 * o], acc[3][2 * o + 1]);
            u64t P = mul2_(mus, mus);
            u64t Q = mul2_(mud, mud);
            u64t PQd = sub2_(P, Q);
            u64t PQs = add2_(P, Q);
            u64t ABd = sub2_(Aq, Bq);
            u64t ABs = add2_(Aq, Bq);
            u64t nl = fma2_(HALF, PQd, C1q);              // (P-Q)/2 + C1
            u64t nr = fma2_(HALF, sub2_(ABd, PQd), C2q);  // (A-B-P+Q)/2 + C2
            u64t dl = fma2_(HALF, PQs, C1q);              // (P+Q)/2 + C1
            u64t dr = fma2_(HALF, sub2_(ABs, PQs), C2q);  // (A+B-P-Q)/2 + C2
            u64t num = mul2_(nl, nr);
            u64t den = mul2_(dl, dr);
            float nlo, nhi, dlo, dhi;
            upk2(num, nlo, nhi);
            upk2(den, dlo, dhi);
            rr[o] = fmaf(nlo, dhi, nhi * dlo);   // nlo/dlo + nhi/dhi
            qq[o] = dlo * dhi;
        }
        float Rt = fmaf(rr[0], qq[1], rr[1] * qq[0]);
        float Qt = qq[0] * qq[1];
        lsum += __fdividef(Rt, Qt);              // one RCP per 4 px
    }

    // -------- Block reduce -> atomic; last block finalizes -------------------
#pragma unroll
    for (int off = 16; off; off >>= 1)
        lsum += __shfl_xor_sync(0xffffffffu, lsum, off);
    if ((tid & 31) == 0) red[tid >> 5] = lsum;
    __syncthreads();
    if (tid == 0) {
        float s = 0.f;
#pragma unroll
        for (int i = 0; i < 8; i++) s += red[i];
        atomicAdd(&g_acc, (double)s);
        __threadfence();
        unsigned int total = gridDim.x * gridDim.y * gridDim.z;
        unsigned int old = atomicAdd(&g_cnt, 1u);
        if (old == total - 1u) {
            double tot = atomicAdd(&g_acc, 0.0);
            out[0] = 1.0f - (float)(tot / 25165824.0);   // 32*3*512*512
            g_acc = 0.0;
            __threadfence();
            g_cnt = 0;
        }
    }
}

extern "C" void kernel_launch(void* const* d_in, const int* in_sizes, int n_in,
                              void* d_out, int out_size) {
    const float* A = (const float*)d_in[0];   // denoised
    const float* B = (const float*)d_in[1];   // clean
    float* out = (float*)d_out;

    dim3 grid(512 / TW, 512 / TH, 32 * 3);    // (16, 16, 96)
    ssim_main_k<<<grid, 256>>>(A, B, out);
}

// round 16
// speedup vs baseline: 1.0712x; 1.0712x over previous
#include <cuda_runtime.h>

// SSIM loss, fused single kernel, f32x2-packed separable 11x11 Gaussian conv.
// 4-channel reformulation: s=cx+cy, d=cx-cy; conv (s, d, s^2, d^2).
//   P=mu_s^2, Q=mu_d^2, A=E[s^2], B=E[d^2]:
//   num = ((P-Q)/2+C1) * ((A-B-P+Q)/2+C2)
//   den = ((P+Q)/2+C1) * ((A+B-P-Q)/2+C2)
// 32x32 tile + halo 5, static SMEM (36.5KB). Phase 2: channel-set split
// items (336, FFMA2). Phase 3: channel-split lanes (half-warp = chset) over
// 8-px windows + shfl.xor(16) butterfly to pair channels -> 36 B/px window
// traffic with all 256 threads active. Fraction tree: 1 RCP per 4 px.

#define TW 32
#define TH 32
#define HALO 5
#define KS 11
#define HWD 42
#define SWX 44            // ss/sd row stride (floats; 8B-aligned float2 rows)
#define S2  22            // sv2 row stride (u64; EVEN -> LDS.128 16B-aligned)

typedef unsigned long long u64t;

__device__ double g_acc = 0.0;
__device__ unsigned int g_cnt = 0;

__device__ constexpr float GW[11] = {
    0.00102838f, 0.00759876f, 0.03600078f, 0.10936069f, 0.21300553f,
    0.26601173f,
    0.21300553f, 0.10936069f, 0.03600078f, 0.00759876f, 0.00102838f};

__device__ __forceinline__ u64t pk2(float lo, float hi) {
    u64t r; asm("mov.b64 %0,{%1,%2};" : "=l"(r) : "f"(lo), "f"(hi)); return r;
}
__device__ __forceinline__ void upk2(u64t v, float& lo, float& hi) {
    asm("mov.b64 {%0,%1},%2;" : "=f"(lo), "=f"(hi) : "l"(v));
}
__device__ __forceinline__ u64t fma2_(u64t a, u64t b, u64t c) {
    u64t d; asm("fma.rn.f32x2 %0,%1,%2,%3;" : "=l"(d) : "l"(a), "l"(b), "l"(c)); return d;
}
__device__ __forceinline__ u64t mul2_(u64t a, u64t b) {
    u64t d; asm("mul.rn.f32x2 %0,%1,%2;" : "=l"(d) : "l"(a), "l"(b)); return d;
}
__device__ __forceinline__ u64t add2_(u64t a, u64t b) {
    u64t d; asm("add.rn.f32x2 %0,%1,%2;" : "=l"(d) : "l"(a), "l"(b)); return d;
}
__device__ __forceinline__ u64t sub2_(u64t a, u64t b) {
    u64t d; asm("sub.rn.f32x2 %0,%1,%2;" : "=l"(d) : "l"(a), "l"(b)); return d;
}

__device__ __forceinline__ constexpr int WS(int j) { return j < 6 ? j : 10 - j; }

__global__ __launch_bounds__(256, 4)
void ssim_main_k(const float* __restrict__ A, const float* __restrict__ Bp,
                 float* __restrict__ out) {
    __shared__ __align__(16) float ss[HWD][SWX];
    __shared__ __align__(16) float sd[HWD][SWX];
    __shared__ __align__(16) u64t  sv2[4][TH][S2];
    __shared__ float red[8];

    const int tid = threadIdx.x;
    const int tx0 = blockIdx.x * TW;
    const int ty0 = blockIdx.y * TH;
    const size_t base = (size_t)blockIdx.z * (512 * 512);

    u64t wq[6];
#pragma unroll
    for (int j = 0; j < 6; j++) wq[j] = pk2(GW[j], GW[j]);

    // -------- Phase 1: halo load (col pairs), clip, s=cx+cy, d=cx-cy --------
    const bool interior = (blockIdx.x != 0) && (blockIdx.x != 15) &&
                          (blockIdx.y != 0) && (blockIdx.y != 15);
    if (interior) {
#pragma unroll
        for (int i = tid; i < 42 * 21; i += 256) {
            int r = i / 21, c2 = i - r * 21;
            size_t idx = base + (size_t)(ty0 + r - HALO) * 512 + (tx0 + 2 * c2 - HALO);
            float cx0 = __saturatef(__ldg(A + idx));
            float cx1 = __saturatef(__ldg(A + idx + 1));
            float cy0 = __saturatef(__ldg(Bp + idx));
            float cy1 = __saturatef(__ldg(Bp + idx + 1));
            *(float2*)&ss[r][2 * c2] = make_float2(cx0 + cy0, cx1 + cy1);
            *(float2*)&sd[r][2 * c2] = make_float2(cx0 - cy0, cx1 - cy1);
        }
    } else {
#pragma unroll
        for (int i = tid; i < 42 * 21; i += 256) {
            int r = i / 21, c2 = i - r * 21;
            int gy = ty0 + r - HALO;
            int gx = tx0 + 2 * c2 - HALO;
            float cx0 = 0.f, cy0 = 0.f, cx1 = 0.f, cy1 = 0.f;
            bool rowok = (unsigned)gy < 512u;
            if (rowok && (unsigned)gx < 512u) {
                size_t idx = base + (size_t)gy * 512 + gx;
                cx0 = __saturatef(__ldg(A + idx));
                cy0 = __saturatef(__ldg(Bp + idx));
            }
            if (rowok && (unsigned)(gx + 1) < 512u) {
                size_t idx = base + (size_t)gy * 512 + gx + 1;
                cx1 = __saturatef(__ldg(A + idx));
                cy1 = __saturatef(__ldg(Bp + idx));
            }
            *(float2*)&ss[r][2 * c2] = make_float2(cx0 + cy0, cx1 + cy1);
            *(float2*)&sd[r][2 * c2] = make_float2(cx0 - cy0, cx1 - cy1);
        }
    }
    __syncthreads();

    // -------- Phase 2: vertical conv, channel-set split items ----------------
    // 336 items = 2 chsets (s | d) x 8 rowgroups (4 rows) x 21 col-pairs.
    for (int i = tid; i < 336; i += 256) {
        const int isD = (i >= 168) ? 1 : 0;
        const int j0 = i - 168 * isD;
        const int g = j0 / 21;
        const int k = j0 - 21 * g;
        const int r0 = g * 4;
        const float* p = isD ? &sd[r0][2 * k] : &ss[r0][2 * k];
        u64t a1[4] = {0, 0, 0, 0}, a2[4] = {0, 0, 0, 0};
#pragma unroll
        for (int p14 = 0; p14 < 14; p14++) {
            float2 vv = *(const float2*)(p + p14 * SWX);
            u64t V = pk2(vv.x, vv.y);
            u64t VV = mul2_(V, V);
#pragma unroll
            for (int o = 0; o < 4; o++) {
                int j = p14 - o;
                if (j >= 0 && j < KS) {
                    u64t w = wq[WS(j)];
                    a1[o] = fma2_(w, V,  a1[o]);
                    a2[o] = fma2_(w, VV, a2[o]);
                }
            }
        }
#pragma unroll
        for (int o = 0; o < 4; o++) {
            int row = r0 + o;
            sv2[isD][row][k]     = a1[o];   // ch0 = mu_s, ch1 = mu_d
            sv2[2 + isD][row][k] = a2[o];   // ch2 = A,    ch3 = B
        }
    }
    __syncthreads();

    // -------- Phase 3: horizontal conv, channel-split + butterfly -----------
    // Warp: lanes 0-15 handle chset s (mu_s, A), lanes 16-31 chset d (mu_d, B)
    // for the same 16 pixel-groups. Group = 8 cols (4 packed outputs); lane
    // computes conv for its 2 channels, then shfl.xor(16) swaps the halves so
    // each lane finalizes SSIM for 2 granules (4 px).
    float lsum = 0.f;
    {
        const int lane = tid & 31;
        const int isD  = lane >> 4;            // 0 = chset s, 1 = chset d
        const int g    = (tid >> 5) * 16 + (lane & 15);   // 0..127
        const int r    = g >> 2;
        const int cg   = g & 3;
        const int m0   = 4 * cg;               // granules m0 .. m0+8 (<= 20)
        u64t mu[4], sq[4];                     // 4 packed conv outputs per ch
#pragma unroll
        for (int cc = 0; cc < 2; cc++) {
            const int ch = isD + 2 * cc;       // cc0: mu chan, cc1: sq chan
            const u64t* rowp = &sv2[ch][r][m0];
            u64t E[9];
            ulonglong2 q0 = *(const ulonglong2*)(rowp);
            ulonglong2 q1 = *(const ulonglong2*)(rowp + 2);
            ulonglong2 q2 = *(const ulonglong2*)(rowp + 4);
            ulonglong2 q3 = *(const ulonglong2*)(rowp + 6);
            E[0] = q0.x; E[1] = q0.y; E[2] = q1.x; E[3] = q1.y;
            E[4] = q2.x; E[5] = q2.y; E[6] = q3.x; E[7] = q3.y;
            E[8] = rowp[8];
            float flo[9], fhi[9];
#pragma unroll
            for (int t = 0; t < 9; t++) upk2(E[t], flo[t], fhi[t]);
            u64t O[8];
#pragma unroll
            for (int t = 0; t < 8; t++) O[t] = pk2(fhi[t], flo[t + 1]);
#pragma unroll
            for (int o = 0; o < 4; o++) {
                u64t a = mul2_(wq[WS(0)], E[o]);
#pragma unroll
                for (int j = 1; j < KS; j++) {
                    u64t v = (j & 1) ? O[o + (j - 1) / 2] : E[o + j / 2];
                    a = fma2_(wq[WS(j)], v, a);
                }
                if (cc == 0) mu[o] = a; else sq[o] = a;
            }
        }
        // Butterfly: send the granules I do NOT finalize (s-lane keeps 0,1;
        // d-lane keeps 2,3), receive partner's complementary channels.
        u64t smu0 = isD ? mu[0] : mu[2];
        u64t smu1 = isD ? mu[1] : mu[3];
        u64t ssq0 = isD ? sq[0] : sq[2];
        u64t ssq1 = isD ? sq[1] : sq[3];
        u64t rmu[2], rsq[2];
        rmu[0] = __shfl_xor_sync(0xffffffffu, smu0, 16);
        rmu[1] = __shfl_xor_sync(0xffffffffu, smu1, 16);
        rsq[0] = __shfl_xor_sync(0xffffffffu, ssq0, 16);
        rsq[1] = __shfl_xor_sync(0xffffffffu, ssq1, 16);

        const u64t HALF = pk2(0.5f, 0.5f);
        const u64t C1q = pk2(1e-4f, 1e-4f);
        const u64t C2q = pk2(9e-4f, 9e-4f);
        float rr[2], qq[2];
#pragma unroll
        for (int o = 0; o < 2; o++) {
            u64t mus = isD ? rmu[o]    : mu[o];
            u64t Aq  = isD ? rsq[o]    : sq[o];
            u64t mud = isD ? mu[2 + o] : rmu[o];
            u64t Bq  = isD ? sq[2 + o] : rsq[o];
            u64t P = mul2_(mus, mus);
            u64t Q = mul2_(mud, mud);
            u64t PQd = sub2_(P, Q);
            u64t PQs = add2_(P, Q);
            u64t ABd = sub2_(Aq, Bq);
            u64t ABs = add2_(Aq, Bq);
            u64t nl = fma2_(HALF, PQd, C1q);              // (P-Q)/2 + C1
            u64t nr = fma2_(HALF, sub2_(ABd, PQd), C2q);  // (A-B-P+Q)/2 + C2
            u64t dl = fma2_(HALF, PQs, C1q);              // (P+Q)/2 + C1
            u64t dr = fma2_(HALF, sub2_(ABs, PQs), C2q);  // (A+B-P-Q)/2 + C2
            u64t num = mul2_(nl, nr);
            u64t den = mul2_(dl, dr);
            float nlo, nhi, dlo, dhi;
            upk2(num, nlo, nhi);
            upk2(den, dlo, dhi);
            rr[o] = fmaf(nlo, dhi, nhi * dlo);   // nlo/dlo + nhi/dhi
            qq[o] = dlo * dhi;
        }
        float Rt = fmaf(rr[0], qq[1], rr[1] * qq[0]);
        float Qt = qq[0] * qq[1];
        lsum += __fdividef(Rt, Qt);              // one RCP per 4 px
    }

    // -------- Block reduce -> atomic; last block finalizes -------------------
#pragma unroll
    for (int off = 16; off; off >>= 1)
        lsum += __shfl_xor_sync(0xffffffffu, lsum, off);
    if ((tid & 31) == 0) red[tid >> 5] = lsum;
    __syncthreads();
    if (tid == 0) {
        float s = 0.f;
#pragma unroll
        for (int i = 0; i < 8; i++) s += red[i];
        atomicAdd(&g_acc, (double)s);
        __threadfence();
        unsigned int total = gridDim.x * gridDim.y * gridDim.z;
        unsigned int old = atomicAdd(&g_cnt, 1u);
        if (old == total - 1u) {
            double tot = atomicAdd(&g_acc, 0.0);
            out[0] = 1.0f - (float)(tot / 25165824.0);   // 32*3*512*512
            g_acc = 0.0;
            __threadfence();
            g_cnt = 0;
        }
    }
}

extern "C" void kernel_launch(void* const* d_in, const int* in_sizes, int n_in,
                              void* d_out, int out_size) {
    const float* A = (const float*)d_in[0];   // denoised
    const float* B = (const float*)d_in[1];   // clean
    float* out = (float*)d_out;

    dim3 grid(512 / TW, 512 / TH, 32 * 3);    // (16, 16, 96)
    ssim_main_k<<<grid, 256>>>(A, B, out);
}